// round 7
// baseline (speedup 1.0000x reference)
#include <cuda_runtime.h>
#include <cuda_bf16.h>

#define BATCH 8
#define SEQ   512
#define HID   1024
#define NHEAD 16
#define HD    64
#define MROWS (BATCH*SEQ)

__device__ float g_q[BATCH*NHEAD*SEQ*HD];
__device__ float g_k[BATCH*NHEAD*SEQ*HD];
__device__ float g_v[BATCH*NHEAD*SEQ*HD];
__device__ float g_attn[BATCH*SEQ*HID];

__device__ __forceinline__ unsigned f2tf(float f) {
    unsigned u;
    asm("cvt.rna.tf32.f32 %0, %1;" : "=r"(u) : "f"(f));
    return u;
}

__device__ __forceinline__ void mma8(float* c, const unsigned* a, const unsigned* b) {
    asm volatile(
        "mma.sync.aligned.m16n8k8.row.col.f32.tf32.tf32.f32 "
        "{%0,%1,%2,%3}, {%4,%5,%6,%7}, {%8,%9}, {%0,%1,%2,%3};"
        : "+f"(c[0]), "+f"(c[1]), "+f"(c[2]), "+f"(c[3])
        : "r"(a[0]), "r"(a[1]), "r"(a[2]), "r"(a[3]), "r"(b[0]), "r"(b[1]));
}

// ===========================================================================
// tf32 tensor-core GEMM (unchanged):
// C[m,n] = scale * (sum_k A[m,k]*W[n,k] + bias[n]); dst 0..2 scatter, 3 plain
// ===========================================================================
#define GBK 16
#define KPAD 20

__global__ __launch_bounds__(256, 2)
void gemm_tf32(const float* __restrict__ A, const float* __restrict__ W,
               const float* __restrict__ bias, float* __restrict__ Cout,
               float scale, int dst)
{
    if (A == nullptr) A = g_attn;

    __shared__ unsigned As[2][128 * KPAD];
    __shared__ unsigned Bs[2][128 * KPAD];

    const int tid = threadIdx.x;
    const int bm = blockIdx.y * 128;
    const int bn = blockIdx.x * 128;
    const int wid = tid >> 5, lane = tid & 31;
    const int wm = (wid >> 2) * 64;
    const int wn = (wid & 3) * 32;
    const int gp = lane >> 2;
    const int tg = lane & 3;

    const int r0 = tid >> 2;
    const int c0 = (tid & 3) * 4;

    const float* A0 = A + (long)(bm + r0)      * 1024 + c0;
    const float* A1 = A + (long)(bm + r0 + 64) * 1024 + c0;
    const float* W0 = W + (long)(bn + r0)      * 1024 + c0;
    const float* W1 = W + (long)(bn + r0 + 64) * 1024 + c0;

    float acc[4][4][4];
    #pragma unroll
    for (int i = 0; i < 4; i++)
        #pragma unroll
        for (int j = 0; j < 4; j++)
            #pragma unroll
            for (int k = 0; k < 4; k++) acc[i][j][k] = 0.f;

    float4 pa0, pa1, pb0, pb1;

#define STS_TILE(BUF) do {                                                   \
    unsigned* as_ = As[BUF]; unsigned* bs_ = Bs[BUF];                        \
    as_[ r0      *KPAD + c0+0] = f2tf(pa0.x);                                \
    as_[ r0      *KPAD + c0+1] = f2tf(pa0.y);                                \
    as_[ r0      *KPAD + c0+2] = f2tf(pa0.z);                                \
    as_[ r0      *KPAD + c0+3] = f2tf(pa0.w);                                \
    as_[(r0+64)  *KPAD + c0+0] = f2tf(pa1.x);                                \
    as_[(r0+64)  *KPAD + c0+1] = f2tf(pa1.y);                                \
    as_[(r0+64)  *KPAD + c0+2] = f2tf(pa1.z);                                \
    as_[(r0+64)  *KPAD + c0+3] = f2tf(pa1.w);                                \
    bs_[ r0      *KPAD + c0+0] = f2tf(pb0.x);                                \
    bs_[ r0      *KPAD + c0+1] = f2tf(pb0.y);                                \
    bs_[ r0      *KPAD + c0+2] = f2tf(pb0.z);                                \
    bs_[ r0      *KPAD + c0+3] = f2tf(pb0.w);                                \
    bs_[(r0+64)  *KPAD + c0+0] = f2tf(pb1.x);                                \
    bs_[(r0+64)  *KPAD + c0+1] = f2tf(pb1.y);                                \
    bs_[(r0+64)  *KPAD + c0+2] = f2tf(pb1.z);                                \
    bs_[(r0+64)  *KPAD + c0+3] = f2tf(pb1.w);                                \
} while (0)

    pa0 = *(const float4*)(A0);
    pa1 = *(const float4*)(A1);
    pb0 = *(const float4*)(W0);
    pb1 = *(const float4*)(W1);
    STS_TILE(0);
    __syncthreads();

    int buf = 0;
    const int KT = 1024 / GBK;
    for (int t = 0; t < KT; ++t) {
        if (t < KT - 1) {
            pa0 = *(const float4*)(A0 + (t + 1) * GBK);
            pa1 = *(const float4*)(A1 + (t + 1) * GBK);
            pb0 = *(const float4*)(W0 + (t + 1) * GBK);
            pb1 = *(const float4*)(W1 + (t + 1) * GBK);
        }
        const unsigned* as = As[buf];
        const unsigned* bs = Bs[buf];
        #pragma unroll
        for (int ks = 0; ks < 2; ks++) {
            const int kb = ks * 8;
            unsigned af[4][4], bf[4][2];
            #pragma unroll
            for (int mf = 0; mf < 4; mf++) {
                const int row = wm + mf * 16 + gp;
                af[mf][0] = as[ row      * KPAD + kb + tg];
                af[mf][1] = as[(row + 8) * KPAD + kb + tg];
                af[mf][2] = as[ row      * KPAD + kb + tg + 4];
                af[mf][3] = as[(row + 8) * KPAD + kb + tg + 4];
            }
            #pragma unroll
            for (int nf = 0; nf < 4; nf++) {
                const int row = wn + nf * 8 + gp;
                bf[nf][0] = bs[row * KPAD + kb + tg];
                bf[nf][1] = bs[row * KPAD + kb + tg + 4];
            }
            #pragma unroll
            for (int mf = 0; mf < 4; mf++)
                #pragma unroll
                for (int nf = 0; nf < 4; nf++)
                    mma8(acc[mf][nf], af[mf], bf[nf]);
        }
        if (t < KT - 1) STS_TILE(buf ^ 1);
        __syncthreads();
        buf ^= 1;
    }
#undef STS_TILE

    float* Cq = (dst == 0) ? g_q : (dst == 1) ? g_k : g_v;

    #pragma unroll
    for (int mf = 0; mf < 4; mf++) {
        #pragma unroll
        for (int nf = 0; nf < 4; nf++) {
            const int n0 = bn + wn + nf * 8 + tg * 2;
            const float b0 = bias[n0], b1 = bias[n0 + 1];
            #pragma unroll
            for (int half = 0; half < 2; half++) {
                const int m = bm + wm + mf * 16 + gp + half * 8;
                const float v0 = (acc[mf][nf][half * 2 + 0] + b0) * scale;
                const float v1 = (acc[mf][nf][half * 2 + 1] + b1) * scale;
                if (dst < 3) {
                    const int b = m >> 9, s = m & 511;
                    const int h = n0 >> 6, d = n0 & 63;
                    const long base = (((long)(b * NHEAD + h)) * SEQ + s) * HD;
                    Cq[base + d]     = v0;
                    Cq[base + d + 1] = v1;
                } else {
                    Cout[(long)m * HID + n0]     = v0;
                    Cout[(long)m * HID + n0 + 1] = v1;
                }
            }
        }
    }
}

// ===========================================================================
// Plain-tf32 mma fused attention. Block = (b, h, 64-query tile). 8 warps,
// warp tile m32 x n16 (mf=2, nf=2).
// smem: sc[64][516] + kv[64][72]  = 150,528 B -> 1 CTA/SM, regs free (<=255).
// K tile uses pitch 68 (phase-1 row-major frag loads conflict-free);
// V tile uses pitch 72 (phase-3 col-major frag loads conflict-free).
// Q fragments persist in 64 registers; all tf32 cvts hoisted out of mma loops.
// ===========================================================================
#define QT   64
#define SCP  516
#define KP1  68
#define VP3  72
#define SMEM_ATTN ((QT*SCP + 64*VP3) * (int)sizeof(float))

__global__ __launch_bounds__(256)
void attn_mma(const float* __restrict__ mask, const float* __restrict__ kg,
              const int* __restrict__ lena, const float* __restrict__ hy,
              const int* __restrict__ layer_p)
{
    extern __shared__ float sm[];
    float*    sc = sm;                              // [64][516]
    unsigned* kv = (unsigned*)(sm + QT * SCP);      // [64][72] (K uses 68 pitch)

    const int tid = threadIdx.x;
    const int bh = blockIdx.x;
    const int b = bh >> 4, h = bh & 15;
    const int q0 = blockIdx.y * QT;

    const long head_off = ((long)(b * NHEAD + h)) * SEQ * HD;

    const int wid = tid >> 5, lane = tid & 31;
    const int g8 = lane >> 2;        // 0..7
    const int tg = lane & 3;         // 0..3
    const int wm = (wid >> 2) * 32;  // 0 or 32 (query rows within tile)
    const int wn = (wid & 3) * 16;   // 0,16,32,48 (cols within 64-wide kt tile)

    // KV tile loader mapping: row = tid>>2 (0..63), 16 consecutive cols
    const int lr = tid >> 2;
    const int lcb = (tid & 3) * 16;

    // ---- hoist Q fragments into registers (whole kernel lifetime) ----
    unsigned qa[2][8][4];
    #pragma unroll
    for (int mf = 0; mf < 2; mf++) {
        const float* q_r0 = g_q + head_off + (long)(q0 + wm + mf * 16 + g8)     * HD;
        const float* q_r1 = g_q + head_off + (long)(q0 + wm + mf * 16 + g8 + 8) * HD;
        #pragma unroll
        for (int kb = 0; kb < 8; kb++) {
            qa[mf][kb][0] = f2tf(q_r0[kb * 8 + tg]);
            qa[mf][kb][1] = f2tf(q_r1[kb * 8 + tg]);
            qa[mf][kb][2] = f2tf(q_r0[kb * 8 + tg + 4]);
            qa[mf][kb][3] = f2tf(q_r1[kb * 8 + tg + 4]);
        }
    }

    // ================= Phase 1: scores = Q K^T + mask =================
    {
        const float* kbase = g_k + head_off + (long)lr * HD + lcb;
        float4 pf[4];
        #pragma unroll
        for (int i = 0; i < 4; i++) pf[i] = *(const float4*)(kbase + i * 4);

        for (int kt = 0; kt < 8; kt++) {
            __syncthreads();
            #pragma unroll
            for (int i = 0; i < 4; i++) {
                unsigned* dst = kv + lr * KP1 + lcb + i * 4;
                dst[0] = f2tf(pf[i].x); dst[1] = f2tf(pf[i].y);
                dst[2] = f2tf(pf[i].z); dst[3] = f2tf(pf[i].w);
            }
            __syncthreads();
            if (kt < 7) {
                const float* nb = kbase + (long)(kt + 1) * 64 * HD;
                #pragma unroll
                for (int i = 0; i < 4; i++) pf[i] = *(const float4*)(nb + i * 4);
            }

            float acc[2][2][4];
            #pragma unroll
            for (int mf = 0; mf < 2; mf++)
                #pragma unroll
                for (int nf = 0; nf < 2; nf++)
                    #pragma unroll
                    for (int k = 0; k < 4; k++) acc[mf][nf][k] = 0.f;

            #pragma unroll
            for (int kb = 0; kb < 8; kb++) {
                unsigned bf[2][2];
                #pragma unroll
                for (int nf = 0; nf < 2; nf++) {
                    const unsigned* base = kv + (wn + nf * 8 + g8) * KP1 + kb * 8 + tg;
                    bf[nf][0] = base[0];
                    bf[nf][1] = base[4];
                }
                #pragma unroll
                for (int mf = 0; mf < 2; mf++)
                    #pragma unroll
                    for (int nf = 0; nf < 2; nf++)
                        mma8(acc[mf][nf], qa[mf][kb], bf[nf]);
            }

            #pragma unroll
            for (int mf = 0; mf < 2; mf++)
                #pragma unroll
                for (int nf = 0; nf < 2; nf++) {
                    const int c = kt * 64 + wn + nf * 8 + 2 * tg;
                    #pragma unroll
                    for (int half = 0; half < 2; half++) {
                        const int r = wm + mf * 16 + g8 + half * 8;
                        const float2 mv = *(const float2*)(mask + ((long)b * SEQ + (q0 + r)) * SEQ + c);
                        float2 sv;
                        sv.x = acc[mf][nf][half * 2 + 0] + mv.x;
                        sv.y = acc[mf][nf][half * 2 + 1] + mv.y;
                        *(float2*)(sc + r * SCP + c) = sv;
                    }
                }
        }
    }
    __syncthreads();

    // ================= Phase 2: softmax + probs mods (write tf32 bits) =====
    {
        const int l  = lena[b];
        const int ly = *layer_p;
        const float ha = hy[ly * 3 + 0];
        const float hb = hy[ly * 3 + 1];
        const float hc = hy[ly * 3 + 2];
        const float* simp = kg + (long)b * 2 * SEQ * SEQ;
        const float* topp = simp + (long)SEQ * SEQ;

        for (int r = wid; r < QT; r += 8) {
            float* row = sc + r * SCP;
            const int qg = q0 + r;

            float mx = -1e30f;
            #pragma unroll 4
            for (int j = lane; j < SEQ; j += 32) mx = fmaxf(mx, row[j]);
            #pragma unroll
            for (int o = 16; o > 0; o >>= 1) mx = fmaxf(mx, __shfl_xor_sync(0xffffffffu, mx, o));

            float s = 0.f;
            #pragma unroll 4
            for (int j = lane; j < SEQ; j += 32) {
                float e = __expf(row[j] - mx);
                row[j] = e;
                s += e;
            }
            #pragma unroll
            for (int o = 16; o > 0; o >>= 1) s += __shfl_xor_sync(0xffffffffu, s, o);
            const float inv = 1.0f / s;

            const bool ra_q = (qg >= 1) && (qg < l - 1);
            const bool ca_q = (qg >= l) && (qg < SEQ - 1);
            const long krow = (long)qg * SEQ;
            #pragma unroll 4
            for (int j = lane; j < SEQ; j += 32) {
                const bool ra_j = (j >= 1) && (j < l - 1);
                const bool ca_j = (j >= l) && (j < SEQ - 1);
                const float lg = ((ra_q && ca_j) || (ra_j && ca_q)) ? hc : 1.0f;
                const float p = row[j] * inv * lg + ha * simp[krow + j] + hb * topp[krow + j];
                row[j] = __uint_as_float(f2tf(p));   // store as tf32 bits
            }
        }
    }

    // ================= Phase 3: out = P V =================
    {
        float oacc[2][2][4];
        #pragma unroll
        for (int mf = 0; mf < 2; mf++)
            #pragma unroll
            for (int nf = 0; nf < 2; nf++)
                #pragma unroll
                for (int k = 0; k < 4; k++) oacc[mf][nf][k] = 0.f;

        const float* vbase = g_v + head_off + (long)lr * HD + lcb;
        float4 pf[4];
        #pragma unroll
        for (int i = 0; i < 4; i++) pf[i] = *(const float4*)(vbase + i * 4);

        for (int kt = 0; kt < 8; kt++) {
            __syncthreads();
            #pragma unroll
            for (int i = 0; i < 4; i++) {
                unsigned* dst = kv + lr * VP3 + lcb + i * 4;
                dst[0] = f2tf(pf[i].x); dst[1] = f2tf(pf[i].y);
                dst[2] = f2tf(pf[i].z); dst[3] = f2tf(pf[i].w);
            }
            __syncthreads();
            if (kt < 7) {
                const float* nb = vbase + (long)(kt + 1) * 64 * HD;
                #pragma unroll
                for (int i = 0; i < 4; i++) pf[i] = *(const float4*)(nb + i * 4);
            }

            #pragma unroll
            for (int kb = 0; kb < 8; kb++) {
                unsigned af[2][4], bf[2][2];
                #pragma unroll
                for (int mf = 0; mf < 2; mf++) {
                    const float* base = sc + (wm + mf * 16 + g8) * SCP + kt * 64 + kb * 8 + tg;
                    af[mf][0] = __float_as_uint(base[0]);
                    af[mf][1] = __float_as_uint(base[8 * SCP]);
                    af[mf][2] = __float_as_uint(base[4]);
                    af[mf][3] = __float_as_uint(base[8 * SCP + 4]);
                }
                #pragma unroll
                for (int nf = 0; nf < 2; nf++) {
                    const unsigned* base = kv + (kb * 8 + tg) * VP3 + wn + nf * 8 + g8;
                    bf[nf][0] = base[0];
                    bf[nf][1] = base[4 * VP3];
                }
                #pragma unroll
                for (int mf = 0; mf < 2; mf++)
                    #pragma unroll
                    for (int nf = 0; nf < 2; nf++)
                        mma8(oacc[mf][nf], af[mf], bf[nf]);
            }
        }

        // epilogue: write O tile to g_attn [B,S,H]
        #pragma unroll
        for (int mf = 0; mf < 2; mf++)
            #pragma unroll
            for (int nf = 0; nf < 2; nf++) {
                const int d0 = wn + nf * 8 + 2 * tg;
                #pragma unroll
                for (int half = 0; half < 2; half++) {
                    const int r = q0 + wm + mf * 16 + g8 + half * 8;
                    float2 ov;
                    ov.x = oacc[mf][nf][half * 2 + 0];
                    ov.y = oacc[mf][nf][half * 2 + 1];
                    *(float2*)(g_attn + ((long)b * SEQ + r) * HID + h * HD + d0) = ov;
                }
            }
    }
}

// ===========================================================================
extern "C" void kernel_launch(void* const* d_in, const int* in_sizes, int n_in,
                              void* d_out, int out_size)
{
    const float* query = (const float*)d_in[0];
    const float* key   = (const float*)d_in[1];
    const float* value = (const float*)d_in[2];
    const float* mask  = (const float*)d_in[3];
    const int*   lena  = (const int*)  d_in[4];
    const float* kg    = (const float*)d_in[5];
    const float* hy    = (const float*)d_in[6];
    const int*   layer = (const int*)  d_in[7];
    const float* Wq    = (const float*)d_in[8];
    const float* bq    = (const float*)d_in[9];
    const float* Wk    = (const float*)d_in[10];
    const float* bk    = (const float*)d_in[11];
    const float* Wv    = (const float*)d_in[12];
    const float* bv    = (const float*)d_in[13];
    const float* Wo    = (const float*)d_in[14];
    const float* bo    = (const float*)d_in[15];
    float* out = (float*)d_out;

    static int smem_set = 0;
    if (!smem_set) {
        cudaFuncSetAttribute(attn_mma,
                             cudaFuncAttributeMaxDynamicSharedMemorySize, SMEM_ATTN);
        smem_set = 1;
    }

    const dim3 ggrid(HID / 128, MROWS / 128);   // (8, 32)
    const float qscale = 0.125f;                // 1/sqrt(64)

    gemm_tf32<<<ggrid, 256>>>(query, Wq, bq, nullptr, qscale, 0);
    gemm_tf32<<<ggrid, 256>>>(key,   Wk, bk, nullptr, 1.0f,   1);
    gemm_tf32<<<ggrid, 256>>>(value, Wv, bv, nullptr, 1.0f,   2);

    dim3 attn_grid(BATCH * NHEAD, SEQ / QT);    // (128, 8)
    attn_mma<<<attn_grid, 256, SMEM_ATTN>>>(mask, kg, lena, hy, layer);

    gemm_tf32<<<ggrid, 256>>>(nullptr, Wo, bo, out, 1.0f, 3);
}

// round 9
// speedup vs baseline: 1.2042x; 1.2042x over previous
#include <cuda_runtime.h>
#include <cuda_bf16.h>

#define BATCH 8
#define SEQ   512
#define HID   1024
#define NHEAD 16
#define HD    64
#define MROWS (BATCH*SEQ)

__device__ float g_q[BATCH*NHEAD*SEQ*HD];
__device__ float g_k[BATCH*NHEAD*SEQ*HD];
__device__ float g_v[BATCH*NHEAD*SEQ*HD];
__device__ float g_attn[BATCH*SEQ*HID];

__device__ __forceinline__ unsigned f2tf(float f) {
    unsigned u;
    asm("cvt.rna.tf32.f32 %0, %1;" : "=r"(u) : "f"(f));
    return u;
}

__device__ __forceinline__ void mma8(float* c, const unsigned* a, const unsigned* b) {
    asm volatile(
        "mma.sync.aligned.m16n8k8.row.col.f32.tf32.tf32.f32 "
        "{%0,%1,%2,%3}, {%4,%5,%6,%7}, {%8,%9}, {%0,%1,%2,%3};"
        : "+f"(c[0]), "+f"(c[1]), "+f"(c[2]), "+f"(c[3])
        : "r"(a[0]), "r"(a[1]), "r"(a[2]), "r"(a[3]), "r"(b[0]), "r"(b[1]));
}

// ===========================================================================
// tf32 tensor-core GEMM (unchanged):
// C[m,n] = scale * (sum_k A[m,k]*W[n,k] + bias[n]); dst 0..2 scatter, 3 plain
// ===========================================================================
#define GBK 16
#define KPAD 20

__global__ __launch_bounds__(256, 2)
void gemm_tf32(const float* __restrict__ A, const float* __restrict__ W,
               const float* __restrict__ bias, float* __restrict__ Cout,
               float scale, int dst)
{
    if (A == nullptr) A = g_attn;

    __shared__ unsigned As[2][128 * KPAD];
    __shared__ unsigned Bs[2][128 * KPAD];

    const int tid = threadIdx.x;
    const int bm = blockIdx.y * 128;
    const int bn = blockIdx.x * 128;
    const int wid = tid >> 5, lane = tid & 31;
    const int wm = (wid >> 2) * 64;
    const int wn = (wid & 3) * 32;
    const int gp = lane >> 2;
    const int tg = lane & 3;

    const int r0 = tid >> 2;
    const int c0 = (tid & 3) * 4;

    const float* A0 = A + (long)(bm + r0)      * 1024 + c0;
    const float* A1 = A + (long)(bm + r0 + 64) * 1024 + c0;
    const float* W0 = W + (long)(bn + r0)      * 1024 + c0;
    const float* W1 = W + (long)(bn + r0 + 64) * 1024 + c0;

    float acc[4][4][4];
    #pragma unroll
    for (int i = 0; i < 4; i++)
        #pragma unroll
        for (int j = 0; j < 4; j++)
            #pragma unroll
            for (int k = 0; k < 4; k++) acc[i][j][k] = 0.f;

    float4 pa0, pa1, pb0, pb1;

#define STS_TILE(BUF) do {                                                   \
    unsigned* as_ = As[BUF]; unsigned* bs_ = Bs[BUF];                        \
    as_[ r0      *KPAD + c0+0] = f2tf(pa0.x);                                \
    as_[ r0      *KPAD + c0+1] = f2tf(pa0.y);                                \
    as_[ r0      *KPAD + c0+2] = f2tf(pa0.z);                                \
    as_[ r0      *KPAD + c0+3] = f2tf(pa0.w);                                \
    as_[(r0+64)  *KPAD + c0+0] = f2tf(pa1.x);                                \
    as_[(r0+64)  *KPAD + c0+1] = f2tf(pa1.y);                                \
    as_[(r0+64)  *KPAD + c0+2] = f2tf(pa1.z);                                \
    as_[(r0+64)  *KPAD + c0+3] = f2tf(pa1.w);                                \
    bs_[ r0      *KPAD + c0+0] = f2tf(pb0.x);                                \
    bs_[ r0      *KPAD + c0+1] = f2tf(pb0.y);                                \
    bs_[ r0      *KPAD + c0+2] = f2tf(pb0.z);                                \
    bs_[ r0      *KPAD + c0+3] = f2tf(pb0.w);                                \
    bs_[(r0+64)  *KPAD + c0+0] = f2tf(pb1.x);                                \
    bs_[(r0+64)  *KPAD + c0+1] = f2tf(pb1.y);                                \
    bs_[(r0+64)  *KPAD + c0+2] = f2tf(pb1.z);                                \
    bs_[(r0+64)  *KPAD + c0+3] = f2tf(pb1.w);                                \
} while (0)

    pa0 = *(const float4*)(A0);
    pa1 = *(const float4*)(A1);
    pb0 = *(const float4*)(W0);
    pb1 = *(const float4*)(W1);
    STS_TILE(0);
    __syncthreads();

    int buf = 0;
    const int KT = 1024 / GBK;
    for (int t = 0; t < KT; ++t) {
        if (t < KT - 1) {
            pa0 = *(const float4*)(A0 + (t + 1) * GBK);
            pa1 = *(const float4*)(A1 + (t + 1) * GBK);
            pb0 = *(const float4*)(W0 + (t + 1) * GBK);
            pb1 = *(const float4*)(W1 + (t + 1) * GBK);
        }
        const unsigned* as = As[buf];
        const unsigned* bs = Bs[buf];
        #pragma unroll
        for (int ks = 0; ks < 2; ks++) {
            const int kb = ks * 8;
            unsigned af[4][4], bf[4][2];
            #pragma unroll
            for (int mf = 0; mf < 4; mf++) {
                const int row = wm + mf * 16 + gp;
                af[mf][0] = as[ row      * KPAD + kb + tg];
                af[mf][1] = as[(row + 8) * KPAD + kb + tg];
                af[mf][2] = as[ row      * KPAD + kb + tg + 4];
                af[mf][3] = as[(row + 8) * KPAD + kb + tg + 4];
            }
            #pragma unroll
            for (int nf = 0; nf < 4; nf++) {
                const int row = wn + nf * 8 + gp;
                bf[nf][0] = bs[row * KPAD + kb + tg];
                bf[nf][1] = bs[row * KPAD + kb + tg + 4];
            }
            #pragma unroll
            for (int mf = 0; mf < 4; mf++)
                #pragma unroll
                for (int nf = 0; nf < 4; nf++)
                    mma8(acc[mf][nf], af[mf], bf[nf]);
        }
        if (t < KT - 1) STS_TILE(buf ^ 1);
        __syncthreads();
        buf ^= 1;
    }
#undef STS_TILE

    float* Cq = (dst == 0) ? g_q : (dst == 1) ? g_k : g_v;

    #pragma unroll
    for (int mf = 0; mf < 4; mf++) {
        #pragma unroll
        for (int nf = 0; nf < 4; nf++) {
            const int n0 = bn + wn + nf * 8 + tg * 2;
            const float b0 = bias[n0], b1 = bias[n0 + 1];
            #pragma unroll
            for (int half = 0; half < 2; half++) {
                const int m = bm + wm + mf * 16 + gp + half * 8;
                const float v0 = (acc[mf][nf][half * 2 + 0] + b0) * scale;
                const float v1 = (acc[mf][nf][half * 2 + 1] + b1) * scale;
                if (dst < 3) {
                    const int b = m >> 9, s = m & 511;
                    const int h = n0 >> 6, d = n0 & 63;
                    const long base = (((long)(b * NHEAD + h)) * SEQ + s) * HD;
                    Cq[base + d]     = v0;
                    Cq[base + d + 1] = v1;
                } else {
                    Cout[(long)m * HID + n0]     = v0;
                    Cout[(long)m * HID + n0 + 1] = v1;
                }
            }
        }
    }
}

// ===========================================================================
// Plain-tf32 mma fused attention (R6 config + LSU diet).
// Block = (b, h, 32-query tile). 8 warps, warp tile m16 x n16.
// smem: sc[32][516] + kv double-buffer 2x[64][72] = 102,912 B -> 2 CTA/SM.
// K tiles use pitch 68 (phase-1 frag loads conflict-free), V tiles pitch 72
// (phase-3 frag loads conflict-free). Packed uint4 STS; 1 barrier per tile.
// ===========================================================================
#define QT   32
#define SCP  516
#define KP   68
#define VP   72
#define KVBUF (64 * 72)
#define SMEM_ATTN ((QT*SCP + 2*KVBUF) * (int)sizeof(float))

__global__ __launch_bounds__(256, 2)
void attn_mma(const float* __restrict__ mask, const float* __restrict__ kg,
              const int* __restrict__ lena, const float* __restrict__ hy,
              const int* __restrict__ layer_p)
{
    extern __shared__ float sm[];
    float*    sc = sm;                              // [32][516]
    unsigned* kv = (unsigned*)(sm + QT * SCP);      // 2 buffers of 64x72

    const int tid = threadIdx.x;
    const int bh = blockIdx.x;
    const int b = bh >> 4, h = bh & 15;
    const int q0 = blockIdx.y * QT;

    const long head_off = ((long)(b * NHEAD + h)) * SEQ * HD;

    const int wid = tid >> 5, lane = tid & 31;
    const int g8 = lane >> 2;        // 0..7
    const int tg = lane & 3;         // 0..3
    const int wm = (wid >> 2) * 16;  // 0 or 16
    const int wn = (wid & 3) * 16;   // 0,16,32,48

    // KV tile loader mapping: row = tid>>2 (0..63), 16 consecutive cols
    const int lr = tid >> 2;
    const int lcb = (tid & 3) * 16;

    // ---- hoist Q fragments into registers ----
    unsigned qa[8][4];
    {
        const float* q_r0 = g_q + head_off + (long)(q0 + wm + g8)     * HD;
        const float* q_r1 = g_q + head_off + (long)(q0 + wm + g8 + 8) * HD;
        #pragma unroll
        for (int kb = 0; kb < 8; kb++) {
            qa[kb][0] = f2tf(q_r0[kb * 8 + tg]);
            qa[kb][1] = f2tf(q_r1[kb * 8 + tg]);
            qa[kb][2] = f2tf(q_r0[kb * 8 + tg + 4]);
            qa[kb][3] = f2tf(q_r1[kb * 8 + tg + 4]);
        }
    }

    // ================= Phase 1: scores = Q K^T + mask =================
    {
        const float* kbase = g_k + head_off + (long)lr * HD + lcb;
        float4 pf[4];
        #pragma unroll
        for (int i = 0; i < 4; i++) pf[i] = *(const float4*)(kbase + i * 4);
        {
            unsigned* dstp = kv + lr * KP + lcb;
            #pragma unroll
            for (int i = 0; i < 4; i++) {
                uint4 pk;
                pk.x = f2tf(pf[i].x); pk.y = f2tf(pf[i].y);
                pk.z = f2tf(pf[i].z); pk.w = f2tf(pf[i].w);
                *(uint4*)(dstp + i * 4) = pk;
            }
        }
        __syncthreads();

        for (int kt = 0; kt < 8; kt++) {
            if (kt < 7) {
                const float* nb = kbase + (long)(kt + 1) * 64 * HD;
                #pragma unroll
                for (int i = 0; i < 4; i++) pf[i] = *(const float4*)(nb + i * 4);
            }
            const unsigned* kbuf = kv + (kt & 1) * KVBUF;

            float acc[2][4];
            #pragma unroll
            for (int nf = 0; nf < 2; nf++)
                #pragma unroll
                for (int k = 0; k < 4; k++) acc[nf][k] = 0.f;

            #pragma unroll
            for (int kb = 0; kb < 8; kb++) {
                unsigned bf[2][2];
                #pragma unroll
                for (int nf = 0; nf < 2; nf++) {
                    const unsigned* base = kbuf + (wn + nf * 8 + g8) * KP + kb * 8 + tg;
                    bf[nf][0] = base[0];
                    bf[nf][1] = base[4];
                }
                #pragma unroll
                for (int nf = 0; nf < 2; nf++)
                    mma8(acc[nf], qa[kb], bf[nf]);
            }

            #pragma unroll
            for (int nf = 0; nf < 2; nf++) {
                const int c = kt * 64 + wn + nf * 8 + 2 * tg;
                #pragma unroll
                for (int half = 0; half < 2; half++) {
                    const int r = wm + g8 + half * 8;
                    const float2 mv = *(const float2*)(mask + ((long)b * SEQ + (q0 + r)) * SEQ + c);
                    float2 sv;
                    sv.x = acc[nf][half * 2 + 0] + mv.x;
                    sv.y = acc[nf][half * 2 + 1] + mv.y;
                    *(float2*)(sc + r * SCP + c) = sv;
                }
            }

            if (kt < 7) {
                unsigned* dstp = kv + ((kt + 1) & 1) * KVBUF + lr * KP + lcb;
                #pragma unroll
                for (int i = 0; i < 4; i++) {
                    uint4 pk;
                    pk.x = f2tf(pf[i].x); pk.y = f2tf(pf[i].y);
                    pk.z = f2tf(pf[i].z); pk.w = f2tf(pf[i].w);
                    *(uint4*)(dstp + i * 4) = pk;
                }
                __syncthreads();
            }
        }
    }
    __syncthreads();

    // ================= Phase 2: softmax + probs mods (float2 passes) =======
    {
        const int l  = lena[b];
        const int ly = *layer_p;
        const float ha = hy[ly * 3 + 0];
        const float hb = hy[ly * 3 + 1];
        const float hc = hy[ly * 3 + 2];
        const float* simp = kg + (long)b * 2 * SEQ * SEQ;
        const float* topp = simp + (long)SEQ * SEQ;

        for (int r = wid; r < QT; r += 8) {
            float* row = sc + r * SCP;
            const int qg = q0 + r;

            float mx = -1e30f;
            #pragma unroll
            for (int j0 = lane * 2; j0 < SEQ; j0 += 64) {
                const float2 v = *(const float2*)(row + j0);
                mx = fmaxf(mx, fmaxf(v.x, v.y));
            }
            #pragma unroll
            for (int o = 16; o > 0; o >>= 1) mx = fmaxf(mx, __shfl_xor_sync(0xffffffffu, mx, o));

            float s = 0.f;
            #pragma unroll
            for (int j0 = lane * 2; j0 < SEQ; j0 += 64) {
                float2 v = *(const float2*)(row + j0);
                v.x = __expf(v.x - mx);
                v.y = __expf(v.y - mx);
                *(float2*)(row + j0) = v;
                s += v.x + v.y;
            }
            #pragma unroll
            for (int o = 16; o > 0; o >>= 1) s += __shfl_xor_sync(0xffffffffu, s, o);
            const float inv = 1.0f / s;

            const bool ra_q = (qg >= 1) && (qg < l - 1);
            const bool ca_q = (qg >= l) && (qg < SEQ - 1);
            const long krow = (long)qg * SEQ;
            #pragma unroll
            for (int j0 = lane * 2; j0 < SEQ; j0 += 64) {
                float2 v = *(const float2*)(row + j0);
                const float2 sv = *(const float2*)(simp + krow + j0);
                const float2 tv = *(const float2*)(topp + krow + j0);
                const int j1 = j0 + 1;
                const bool ra_0 = (j0 >= 1) && (j0 < l - 1);
                const bool ca_0 = (j0 >= l) && (j0 < SEQ - 1);
                const bool ra_1 = (j1 >= 1) && (j1 < l - 1);
                const bool ca_1 = (j1 >= l) && (j1 < SEQ - 1);
                const float lg0 = ((ra_q && ca_0) || (ra_0 && ca_q)) ? hc : 1.0f;
                const float lg1 = ((ra_q && ca_1) || (ra_1 && ca_q)) ? hc : 1.0f;
                float2 p;
                p.x = __uint_as_float(f2tf(v.x * inv * lg0 + ha * sv.x + hb * tv.x));
                p.y = __uint_as_float(f2tf(v.y * inv * lg1 + ha * sv.y + hb * tv.y));
                *(float2*)(row + j0) = p;
            }
        }
    }

    // ================= Phase 3: out = P V =================
    {
        float oacc[2][4];
        #pragma unroll
        for (int nf = 0; nf < 2; nf++)
            #pragma unroll
            for (int k = 0; k < 4; k++) oacc[nf][k] = 0.f;

        const float* vbase = g_v + head_off + (long)lr * HD + lcb;
        float4 pf[4];
        #pragma unroll
        for (int i = 0; i < 4; i++) pf[i] = *(const float4*)(vbase + i * 4);
        __syncthreads();   // phase-2 done everywhere before kv reuse
        {
            unsigned* dstp = kv + lr * VP + lcb;
            #pragma unroll
            for (int i = 0; i < 4; i++) {
                uint4 pk;
                pk.x = f2tf(pf[i].x); pk.y = f2tf(pf[i].y);
                pk.z = f2tf(pf[i].z); pk.w = f2tf(pf[i].w);
                *(uint4*)(dstp + i * 4) = pk;
            }
        }
        __syncthreads();

        for (int kt = 0; kt < 8; kt++) {
            if (kt < 7) {
                const float* nb = vbase + (long)(kt + 1) * 64 * HD;
                #pragma unroll
                for (int i = 0; i < 4; i++) pf[i] = *(const float4*)(nb + i * 4);
            }
            const unsigned* vbuf = kv + (kt & 1) * KVBUF;

            #pragma unroll
            for (int kb = 0; kb < 8; kb++) {
                unsigned af[4], bf[2][2];
                {
                    const float* base = sc + (wm + g8) * SCP + kt * 64 + kb * 8 + tg;
                    af[0] = __float_as_uint(base[0]);
                    af[1] = __float_as_uint(base[8 * SCP]);
                    af[2] = __float_as_uint(base[4]);
                    af[3] = __float_as_uint(base[8 * SCP + 4]);
                }
                #pragma unroll
                for (int nf = 0; nf < 2; nf++) {
                    const unsigned* base = vbuf + (kb * 8 + tg) * VP + wn + nf * 8 + g8;
                    bf[nf][0] = base[0];
                    bf[nf][1] = base[4 * VP];
                }
                #pragma unroll
                for (int nf = 0; nf < 2; nf++)
                    mma8(oacc[nf], af, bf[nf]);
            }

            if (kt < 7) {
                unsigned* dstp = kv + ((kt + 1) & 1) * KVBUF + lr * VP + lcb;
                #pragma unroll
                for (int i = 0; i < 4; i++) {
                    uint4 pk;
                    pk.x = f2tf(pf[i].x); pk.y = f2tf(pf[i].y);
                    pk.z = f2tf(pf[i].z); pk.w = f2tf(pf[i].w);
                    *(uint4*)(dstp + i * 4) = pk;
                }
                __syncthreads();
            }
        }

        // epilogue
        #pragma unroll
        for (int nf = 0; nf < 2; nf++) {
            const int d0 = wn + nf * 8 + 2 * tg;
            #pragma unroll
            for (int half = 0; half < 2; half++) {
                const int r = q0 + wm + g8 + half * 8;
                float2 ov;
                ov.x = oacc[nf][half * 2 + 0];
                ov.y = oacc[nf][half * 2 + 1];
                *(float2*)(g_attn + ((long)b * SEQ + r) * HID + h * HD + d0) = ov;
            }
        }
    }
}

// ===========================================================================
extern "C" void kernel_launch(void* const* d_in, const int* in_sizes, int n_in,
                              void* d_out, int out_size)
{
    const float* query = (const float*)d_in[0];
    const float* key   = (const float*)d_in[1];
    const float* value = (const float*)d_in[2];
    const float* mask  = (const float*)d_in[3];
    const int*   lena  = (const int*)  d_in[4];
    const float* kg    = (const float*)d_in[5];
    const float* hy    = (const float*)d_in[6];
    const int*   layer = (const int*)  d_in[7];
    const float* Wq    = (const float*)d_in[8];
    const float* bq    = (const float*)d_in[9];
    const float* Wk    = (const float*)d_in[10];
    const float* bk    = (const float*)d_in[11];
    const float* Wv    = (const float*)d_in[12];
    const float* bv    = (const float*)d_in[13];
    const float* Wo    = (const float*)d_in[14];
    const float* bo    = (const float*)d_in[15];
    float* out = (float*)d_out;

    static int smem_set = 0;
    if (!smem_set) {
        cudaFuncSetAttribute(attn_mma,
                             cudaFuncAttributeMaxDynamicSharedMemorySize, SMEM_ATTN);
        smem_set = 1;
    }

    const dim3 ggrid(HID / 128, MROWS / 128);   // (8, 32)
    const float qscale = 0.125f;                // 1/sqrt(64)

    gemm_tf32<<<ggrid, 256>>>(query, Wq, bq, nullptr, qscale, 0);
    gemm_tf32<<<ggrid, 256>>>(key,   Wk, bk, nullptr, 1.0f,   1);
    gemm_tf32<<<ggrid, 256>>>(value, Wv, bv, nullptr, 1.0f,   2);

    dim3 attn_grid(BATCH * NHEAD, SEQ / QT);    // (128, 16)
    attn_mma<<<attn_grid, 256, SMEM_ATTN>>>(mask, kg, lena, hy, layer);

    gemm_tf32<<<ggrid, 256>>>(nullptr, Wo, bo, out, 1.0f, 3);
}

// round 10
// speedup vs baseline: 1.2963x; 1.0765x over previous
#include <cuda_runtime.h>
#include <cuda_bf16.h>

#define BATCH 8
#define SEQ   512
#define HID   1024
#define NHEAD 16
#define HD    64
#define MROWS (BATCH*SEQ)

__device__ float g_q[BATCH*NHEAD*SEQ*HD];
__device__ float g_k[BATCH*NHEAD*SEQ*HD];
__device__ float g_v[BATCH*NHEAD*SEQ*HD];
__device__ float g_attn[BATCH*SEQ*HID];

__device__ __forceinline__ unsigned f2tf(float f) {
    unsigned u;
    asm("cvt.rna.tf32.f32 %0, %1;" : "=r"(u) : "f"(f));
    return u;
}

__device__ __forceinline__ void mma8(float* c, const unsigned* a, const unsigned* b) {
    asm volatile(
        "mma.sync.aligned.m16n8k8.row.col.f32.tf32.tf32.f32 "
        "{%0,%1,%2,%3}, {%4,%5,%6,%7}, {%8,%9}, {%0,%1,%2,%3};"
        : "+f"(c[0]), "+f"(c[1]), "+f"(c[2]), "+f"(c[3])
        : "r"(a[0]), "r"(a[1]), "r"(a[2]), "r"(a[3]), "r"(b[0]), "r"(b[1]));
}

__device__ __forceinline__ void cp_async16(unsigned saddr, const void* gptr) {
    asm volatile("cp.async.cg.shared.global [%0], [%1], 16;"
                 :: "r"(saddr), "l"(gptr));
}
__device__ __forceinline__ void cp_commit() {
    asm volatile("cp.async.commit_group;");
}
__device__ __forceinline__ void cp_wait0() {
    asm volatile("cp.async.wait_group 0;");
}

// ===========================================================================
// tf32 tensor-core GEMM (unchanged):
// C[m,n] = scale * (sum_k A[m,k]*W[n,k] + bias[n]); dst 0..2 scatter, 3 plain
// ===========================================================================
#define GBK 16
#define KPAD 20

__global__ __launch_bounds__(256, 2)
void gemm_tf32(const float* __restrict__ A, const float* __restrict__ W,
               const float* __restrict__ bias, float* __restrict__ Cout,
               float scale, int dst)
{
    if (A == nullptr) A = g_attn;

    __shared__ unsigned As[2][128 * KPAD];
    __shared__ unsigned Bs[2][128 * KPAD];

    const int tid = threadIdx.x;
    const int bm = blockIdx.y * 128;
    const int bn = blockIdx.x * 128;
    const int wid = tid >> 5, lane = tid & 31;
    const int wm = (wid >> 2) * 64;
    const int wn = (wid & 3) * 32;
    const int gp = lane >> 2;
    const int tg = lane & 3;

    const int r0 = tid >> 2;
    const int c0 = (tid & 3) * 4;

    const float* A0 = A + (long)(bm + r0)      * 1024 + c0;
    const float* A1 = A + (long)(bm + r0 + 64) * 1024 + c0;
    const float* W0 = W + (long)(bn + r0)      * 1024 + c0;
    const float* W1 = W + (long)(bn + r0 + 64) * 1024 + c0;

    float acc[4][4][4];
    #pragma unroll
    for (int i = 0; i < 4; i++)
        #pragma unroll
        for (int j = 0; j < 4; j++)
            #pragma unroll
            for (int k = 0; k < 4; k++) acc[i][j][k] = 0.f;

    float4 pa0, pa1, pb0, pb1;

#define STS_TILE(BUF) do {                                                   \
    unsigned* as_ = As[BUF]; unsigned* bs_ = Bs[BUF];                        \
    as_[ r0      *KPAD + c0+0] = f2tf(pa0.x);                                \
    as_[ r0      *KPAD + c0+1] = f2tf(pa0.y);                                \
    as_[ r0      *KPAD + c0+2] = f2tf(pa0.z);                                \
    as_[ r0      *KPAD + c0+3] = f2tf(pa0.w);                                \
    as_[(r0+64)  *KPAD + c0+0] = f2tf(pa1.x);                                \
    as_[(r0+64)  *KPAD + c0+1] = f2tf(pa1.y);                                \
    as_[(r0+64)  *KPAD + c0+2] = f2tf(pa1.z);                                \
    as_[(r0+64)  *KPAD + c0+3] = f2tf(pa1.w);                                \
    bs_[ r0      *KPAD + c0+0] = f2tf(pb0.x);                                \
    bs_[ r0      *KPAD + c0+1] = f2tf(pb0.y);                                \
    bs_[ r0      *KPAD + c0+2] = f2tf(pb0.z);                                \
    bs_[ r0      *KPAD + c0+3] = f2tf(pb0.w);                                \
    bs_[(r0+64)  *KPAD + c0+0] = f2tf(pb1.x);                                \
    bs_[(r0+64)  *KPAD + c0+1] = f2tf(pb1.y);                                \
    bs_[(r0+64)  *KPAD + c0+2] = f2tf(pb1.z);                                \
    bs_[(r0+64)  *KPAD + c0+3] = f2tf(pb1.w);                                \
} while (0)

    pa0 = *(const float4*)(A0);
    pa1 = *(const float4*)(A1);
    pb0 = *(const float4*)(W0);
    pb1 = *(const float4*)(W1);
    STS_TILE(0);
    __syncthreads();

    int buf = 0;
    const int KT = 1024 / GBK;
    for (int t = 0; t < KT; ++t) {
        if (t < KT - 1) {
            pa0 = *(const float4*)(A0 + (t + 1) * GBK);
            pa1 = *(const float4*)(A1 + (t + 1) * GBK);
            pb0 = *(const float4*)(W0 + (t + 1) * GBK);
            pb1 = *(const float4*)(W1 + (t + 1) * GBK);
        }
        const unsigned* as = As[buf];
        const unsigned* bs = Bs[buf];
        #pragma unroll
        for (int ks = 0; ks < 2; ks++) {
            const int kb = ks * 8;
            unsigned af[4][4], bf[4][2];
            #pragma unroll
            for (int mf = 0; mf < 4; mf++) {
                const int row = wm + mf * 16 + gp;
                af[mf][0] = as[ row      * KPAD + kb + tg];
                af[mf][1] = as[(row + 8) * KPAD + kb + tg];
                af[mf][2] = as[ row      * KPAD + kb + tg + 4];
                af[mf][3] = as[(row + 8) * KPAD + kb + tg + 4];
            }
            #pragma unroll
            for (int nf = 0; nf < 4; nf++) {
                const int row = wn + nf * 8 + gp;
                bf[nf][0] = bs[row * KPAD + kb + tg];
                bf[nf][1] = bs[row * KPAD + kb + tg + 4];
            }
            #pragma unroll
            for (int mf = 0; mf < 4; mf++)
                #pragma unroll
                for (int nf = 0; nf < 4; nf++)
                    mma8(acc[mf][nf], af[mf], bf[nf]);
        }
        if (t < KT - 1) STS_TILE(buf ^ 1);
        __syncthreads();
        buf ^= 1;
    }
#undef STS_TILE

    float* Cq = (dst == 0) ? g_q : (dst == 1) ? g_k : g_v;

    #pragma unroll
    for (int mf = 0; mf < 4; mf++) {
        #pragma unroll
        for (int nf = 0; nf < 4; nf++) {
            const int n0 = bn + wn + nf * 8 + tg * 2;
            const float b0 = bias[n0], b1 = bias[n0 + 1];
            #pragma unroll
            for (int half = 0; half < 2; half++) {
                const int m = bm + wm + mf * 16 + gp + half * 8;
                const float v0 = (acc[mf][nf][half * 2 + 0] + b0) * scale;
                const float v1 = (acc[mf][nf][half * 2 + 1] + b1) * scale;
                if (dst < 3) {
                    const int b = m >> 9, s = m & 511;
                    const int h = n0 >> 6, d = n0 & 63;
                    const long base = (((long)(b * NHEAD + h)) * SEQ + s) * HD;
                    Cq[base + d]     = v0;
                    Cq[base + d + 1] = v1;
                } else {
                    Cout[(long)m * HID + n0]     = v0;
                    Cout[(long)m * HID + n0 + 1] = v1;
                }
            }
        }
    }
}

// ===========================================================================
// tf32 mma fused attention. QT=32, 2 CTA/SM, double-buffered K/V via cp.async.
// K/V tiles land in smem as RAW fp32; mma.tf32 reads the top 19 bits
// (implicit truncation) — probs/Q keep rounded cvt (outside hot loops).
// smem: sc[32][516] + kv 2x[64][72] = 102,912 B.
// ===========================================================================
#define QT   32
#define SCP  516
#define KP   68
#define VP   72
#define KVBUF (64 * 72)
#define SMEM_ATTN ((QT*SCP + 2*KVBUF) * (int)sizeof(float))

__global__ __launch_bounds__(256, 2)
void attn_mma(const float* __restrict__ mask, const float* __restrict__ kg,
              const int* __restrict__ lena, const float* __restrict__ hy,
              const int* __restrict__ layer_p)
{
    extern __shared__ float sm[];
    float*    sc = sm;                              // [32][516]
    unsigned* kv = (unsigned*)(sm + QT * SCP);      // 2 buffers of 64x72

    const unsigned kv_u32 = (unsigned)__cvta_generic_to_shared(kv);

    const int tid = threadIdx.x;
    const int bh = blockIdx.x;
    const int b = bh >> 4, h = bh & 15;
    const int q0 = blockIdx.y * QT;

    const long head_off = ((long)(b * NHEAD + h)) * SEQ * HD;

    const int wid = tid >> 5, lane = tid & 31;
    const int g8 = lane >> 2;        // 0..7
    const int tg = lane & 3;         // 0..3
    const int wm = (wid >> 2) * 16;  // 0 or 16
    const int wn = (wid & 3) * 16;   // 0,16,32,48

    // KV tile loader mapping: row = tid>>2 (0..63), 16 consecutive cols
    const int lr = tid >> 2;
    const int lcb = (tid & 3) * 16;

    // ---- hoist Q fragments into registers ----
    unsigned qa[8][4];
    {
        const float* q_r0 = g_q + head_off + (long)(q0 + wm + g8)     * HD;
        const float* q_r1 = g_q + head_off + (long)(q0 + wm + g8 + 8) * HD;
        #pragma unroll
        for (int kb = 0; kb < 8; kb++) {
            qa[kb][0] = f2tf(q_r0[kb * 8 + tg]);
            qa[kb][1] = f2tf(q_r1[kb * 8 + tg]);
            qa[kb][2] = f2tf(q_r0[kb * 8 + tg + 4]);
            qa[kb][3] = f2tf(q_r1[kb * 8 + tg + 4]);
        }
    }

    // ================= Phase 1: scores = Q K^T + mask =================
    {
        const float* kbase = g_k + head_off + (long)lr * HD + lcb;
        const unsigned kdst = kv_u32 + (unsigned)((lr * KP + lcb) * 4);

        // prologue: copy K tile 0 into buffer 0
        #pragma unroll
        for (int i = 0; i < 4; i++)
            cp_async16(kdst + i * 16, kbase + i * 4);
        cp_commit();
        cp_wait0();
        __syncthreads();

        for (int kt = 0; kt < 8; kt++) {
            if (kt < 7) {
                const unsigned d = kv_u32 + (unsigned)(((kt + 1) & 1) * KVBUF * 4)
                                 + (unsigned)((lr * KP + lcb) * 4);
                const float* s = kbase + (long)(kt + 1) * 64 * HD;
                #pragma unroll
                for (int i = 0; i < 4; i++)
                    cp_async16(d + i * 16, s + i * 4);
                cp_commit();
            }
            const unsigned* kbuf = kv + (kt & 1) * KVBUF;

            float acc[2][4];
            #pragma unroll
            for (int nf = 0; nf < 2; nf++)
                #pragma unroll
                for (int k = 0; k < 4; k++) acc[nf][k] = 0.f;

            #pragma unroll
            for (int kb = 0; kb < 8; kb++) {
                unsigned bf[2][2];
                #pragma unroll
                for (int nf = 0; nf < 2; nf++) {
                    const unsigned* base = kbuf + (wn + nf * 8 + g8) * KP + kb * 8 + tg;
                    bf[nf][0] = base[0];
                    bf[nf][1] = base[4];
                }
                #pragma unroll
                for (int nf = 0; nf < 2; nf++)
                    mma8(acc[nf], qa[kb], bf[nf]);
            }

            #pragma unroll
            for (int nf = 0; nf < 2; nf++) {
                const int c = kt * 64 + wn + nf * 8 + 2 * tg;
                #pragma unroll
                for (int half = 0; half < 2; half++) {
                    const int r = wm + g8 + half * 8;
                    const float2 mv = *(const float2*)(mask + ((long)b * SEQ + (q0 + r)) * SEQ + c);
                    float2 sv;
                    sv.x = acc[nf][half * 2 + 0] + mv.x;
                    sv.y = acc[nf][half * 2 + 1] + mv.y;
                    *(float2*)(sc + r * SCP + c) = sv;
                }
            }

            if (kt < 7) {
                cp_wait0();
                __syncthreads();
            }
        }
    }
    __syncthreads();

    // ================= Phase 2: softmax + probs mods (float2 passes) =======
    {
        const int l  = lena[b];
        const int ly = *layer_p;
        const float ha = hy[ly * 3 + 0];
        const float hb = hy[ly * 3 + 1];
        const float hc = hy[ly * 3 + 2];
        const float* simp = kg + (long)b * 2 * SEQ * SEQ;
        const float* topp = simp + (long)SEQ * SEQ;

        for (int r = wid; r < QT; r += 8) {
            float* row = sc + r * SCP;
            const int qg = q0 + r;

            float mx = -1e30f;
            #pragma unroll
            for (int j0 = lane * 2; j0 < SEQ; j0 += 64) {
                const float2 v = *(const float2*)(row + j0);
                mx = fmaxf(mx, fmaxf(v.x, v.y));
            }
            #pragma unroll
            for (int o = 16; o > 0; o >>= 1) mx = fmaxf(mx, __shfl_xor_sync(0xffffffffu, mx, o));

            float s = 0.f;
            #pragma unroll
            for (int j0 = lane * 2; j0 < SEQ; j0 += 64) {
                float2 v = *(const float2*)(row + j0);
                v.x = __expf(v.x - mx);
                v.y = __expf(v.y - mx);
                *(float2*)(row + j0) = v;
                s += v.x + v.y;
            }
            #pragma unroll
            for (int o = 16; o > 0; o >>= 1) s += __shfl_xor_sync(0xffffffffu, s, o);
            const float inv = 1.0f / s;

            const bool ra_q = (qg >= 1) && (qg < l - 1);
            const bool ca_q = (qg >= l) && (qg < SEQ - 1);
            const long krow = (long)qg * SEQ;
            #pragma unroll
            for (int j0 = lane * 2; j0 < SEQ; j0 += 64) {
                float2 v = *(const float2*)(row + j0);
                const float2 sv = *(const float2*)(simp + krow + j0);
                const float2 tv = *(const float2*)(topp + krow + j0);
                const int j1 = j0 + 1;
                const bool ra_0 = (j0 >= 1) && (j0 < l - 1);
                const bool ca_0 = (j0 >= l) && (j0 < SEQ - 1);
                const bool ra_1 = (j1 >= 1) && (j1 < l - 1);
                const bool ca_1 = (j1 >= l) && (j1 < SEQ - 1);
                const float lg0 = ((ra_q && ca_0) || (ra_0 && ca_q)) ? hc : 1.0f;
                const float lg1 = ((ra_q && ca_1) || (ra_1 && ca_q)) ? hc : 1.0f;
                float2 p;
                p.x = __uint_as_float(f2tf(v.x * inv * lg0 + ha * sv.x + hb * tv.x));
                p.y = __uint_as_float(f2tf(v.y * inv * lg1 + ha * sv.y + hb * tv.y));
                *(float2*)(row + j0) = p;
            }
        }
    }

    // ================= Phase 3: out = P V =================
    {
        float oacc[2][4];
        #pragma unroll
        for (int nf = 0; nf < 2; nf++)
            #pragma unroll
            for (int k = 0; k < 4; k++) oacc[nf][k] = 0.f;

        const float* vbase = g_v + head_off + (long)lr * HD + lcb;
        const unsigned vdst = kv_u32 + (unsigned)((lr * VP + lcb) * 4);

        // prologue: copy V tile 0 into buffer 0 (kv last read at phase-1 end,
        // all threads past the phase-1 closing barrier)
        #pragma unroll
        for (int i = 0; i < 4; i++)
            cp_async16(vdst + i * 16, vbase + i * 4);
        cp_commit();
        cp_wait0();
        __syncthreads();   // covers phase-2 sc writes AND V tile 0 visibility

        for (int kt = 0; kt < 8; kt++) {
            if (kt < 7) {
                const unsigned d = kv_u32 + (unsigned)(((kt + 1) & 1) * KVBUF * 4)
                                 + (unsigned)((lr * VP + lcb) * 4);
                const float* s = vbase + (long)(kt + 1) * 64 * HD;
                #pragma unroll
                for (int i = 0; i < 4; i++)
                    cp_async16(d + i * 16, s + i * 4);
                cp_commit();
            }
            const unsigned* vbuf = kv + (kt & 1) * KVBUF;

            #pragma unroll
            for (int kb = 0; kb < 8; kb++) {
                unsigned af[4], bf[2][2];
                {
                    const float* base = sc + (wm + g8) * SCP + kt * 64 + kb * 8 + tg;
                    af[0] = __float_as_uint(base[0]);
                    af[1] = __float_as_uint(base[8 * SCP]);
                    af[2] = __float_as_uint(base[4]);
                    af[3] = __float_as_uint(base[8 * SCP + 4]);
                }
                #pragma unroll
                for (int nf = 0; nf < 2; nf++) {
                    const unsigned* base = vbuf + (kb * 8 + tg) * VP + wn + nf * 8 + g8;
                    bf[nf][0] = base[0];
                    bf[nf][1] = base[4 * VP];
                }
                #pragma unroll
                for (int nf = 0; nf < 2; nf++)
                    mma8(oacc[nf], af, bf[nf]);
            }

            if (kt < 7) {
                cp_wait0();
                __syncthreads();
            }
        }

        // epilogue
        #pragma unroll
        for (int nf = 0; nf < 2; nf++) {
            const int d0 = wn + nf * 8 + 2 * tg;
            #pragma unroll
            for (int half = 0; half < 2; half++) {
                const int r = q0 + wm + g8 + half * 8;
                float2 ov;
                ov.x = oacc[nf][half * 2 + 0];
                ov.y = oacc[nf][half * 2 + 1];
                *(float2*)(g_attn + ((long)b * SEQ + r) * HID + h * HD + d0) = ov;
            }
        }
    }
}

// ===========================================================================
extern "C" void kernel_launch(void* const* d_in, const int* in_sizes, int n_in,
                              void* d_out, int out_size)
{
    const float* query = (const float*)d_in[0];
    const float* key   = (const float*)d_in[1];
    const float* value = (const float*)d_in[2];
    const float* mask  = (const float*)d_in[3];
    const int*   lena  = (const int*)  d_in[4];
    const float* kg    = (const float*)d_in[5];
    const float* hy    = (const float*)d_in[6];
    const int*   layer = (const int*)  d_in[7];
    const float* Wq    = (const float*)d_in[8];
    const float* bq    = (const float*)d_in[9];
    const float* Wk    = (const float*)d_in[10];
    const float* bk    = (const float*)d_in[11];
    const float* Wv    = (const float*)d_in[12];
    const float* bv    = (const float*)d_in[13];
    const float* Wo    = (const float*)d_in[14];
    const float* bo    = (const float*)d_in[15];
    float* out = (float*)d_out;

    static int smem_set = 0;
    if (!smem_set) {
        cudaFuncSetAttribute(attn_mma,
                             cudaFuncAttributeMaxDynamicSharedMemorySize, SMEM_ATTN);
        smem_set = 1;
    }

    const dim3 ggrid(HID / 128, MROWS / 128);   // (8, 32)
    const float qscale = 0.125f;                // 1/sqrt(64)

    gemm_tf32<<<ggrid, 256>>>(query, Wq, bq, nullptr, qscale, 0);
    gemm_tf32<<<ggrid, 256>>>(key,   Wk, bk, nullptr, 1.0f,   1);
    gemm_tf32<<<ggrid, 256>>>(value, Wv, bv, nullptr, 1.0f,   2);

    dim3 attn_grid(BATCH * NHEAD, SEQ / QT);    // (128, 16)
    attn_mma<<<attn_grid, 256, SMEM_ATTN>>>(mask, kg, lena, hy, layer);

    gemm_tf32<<<ggrid, 256>>>(nullptr, Wo, bo, out, 1.0f, 3);
}